// round 3
// baseline (speedup 1.0000x reference)
#include <cuda_runtime.h>
#include <cstdint>
#include <cstddef>

#define BB 128
#define TT 128
#define HH 1024
#define H3 3072

// Scratch (static device globals -- no dynamic allocation allowed).
__device__ float    g_xp[50331648ULL];          // [T][B][3H] fp32 (192 MB)
__device__ uint32_t g_whtf[2ULL * 3 * HH * HH]; // Wh pre-converted to tf32 (25 MB)
__device__ float    g_hbuf[2 * BB * HH];        // double-buffered h (fp32)
__device__ uint32_t g_htf[2 * BB * HH];         // double-buffered h (tf32)

__device__ __forceinline__ uint32_t f2tf(float f) {
    uint32_t u;
    asm("cvt.rna.tf32.f32 %0, %1;" : "=r"(u) : "f"(f));
    return u;
}

__device__ __forceinline__ void mma_tf32(float d[4], const uint32_t a[4], const uint32_t b[2]) {
    asm volatile(
        "mma.sync.aligned.m16n8k8.row.col.f32.tf32.tf32.f32 "
        "{%0,%1,%2,%3}, {%4,%5,%6,%7}, {%8,%9}, {%0,%1,%2,%3};"
        : "+f"(d[0]), "+f"(d[1]), "+f"(d[2]), "+f"(d[3])
        : "r"(a[0]), "r"(a[1]), "r"(a[2]), "r"(a[3]), "r"(b[0]), "r"(b[1]));
}

__device__ __forceinline__ void ldsm4(uint32_t& r0, uint32_t& r1, uint32_t& r2, uint32_t& r3,
                                      uint32_t addr) {
    asm volatile("ldmatrix.sync.aligned.m8n8.x4.shared.b16 {%0,%1,%2,%3}, [%4];"
                 : "=r"(r0), "=r"(r1), "=r"(r2), "=r"(r3) : "r"(addr));
}

// ---------------------------------------------------------------------------
// Elementwise fp32 -> tf32 conversion (vectorized x4).
// ---------------------------------------------------------------------------
__global__ void cvt_tf32_kernel(const float* __restrict__ src, uint32_t* __restrict__ dst, int n4)
{
    int i = blockIdx.x * blockDim.x + threadIdx.x;
    if (i < n4) {
        float4 v = ((const float4*)src)[i];
        uint4 o;
        o.x = f2tf(v.x); o.y = f2tf(v.y); o.z = f2tf(v.z); o.w = f2tf(v.w);
        ((uint4*)dst)[i] = o;
    }
}

// ---------------------------------------------------------------------------
// xproj: C[m][n] = sum_k A[m][k] * W[n][k] + bias[n]   (unchanged)
// ---------------------------------------------------------------------------
#define XST 20

__global__ __launch_bounds__(256) void xproj_kernel(
    const float* __restrict__ cur, const float* __restrict__ W,
    const float* __restrict__ bias, float* __restrict__ xp)
{
    __shared__ uint32_t As[2][128 * XST];
    __shared__ uint32_t Bs[2][128 * XST];

    const int tid  = threadIdx.x;
    const int lane = tid & 31;
    const int wid  = tid >> 5;
    const int wm   = (wid >> 2) * 64;
    const int wn   = (wid & 3) * 32;
    const int m0   = blockIdx.y * 128;
    const int n0   = blockIdx.x * 128;

    const float* gp[4];
    int soff[2];
    #pragma unroll
    for (int i = 0; i < 2; i++) {
        int idx = tid + i * 256;
        int row = idx >> 2, kv = idx & 3;
        int m = m0 + row;
        int b = m & (BB - 1);
        int t = m >> 7;
        gp[i]     = cur + ((size_t)b * TT + t) * HH + kv * 4;
        gp[2 + i] = W + (size_t)(n0 + row) * HH + kv * 4;
        soff[i]   = row * XST + kv * 4;
    }

    float acc[4][4][4];
    #pragma unroll
    for (int a = 0; a < 4; a++)
        #pragma unroll
        for (int b = 0; b < 4; b++)
            #pragma unroll
            for (int c = 0; c < 4; c++) acc[a][b][c] = 0.f;

    float4 rv[4];
    #pragma unroll
    for (int i = 0; i < 4; i++) rv[i] = *(const float4*)(gp[i]);
    #pragma unroll
    for (int i = 0; i < 2; i++) {
        uint32_t* p = &As[0][soff[i]];
        p[0] = f2tf(rv[i].x); p[1] = f2tf(rv[i].y); p[2] = f2tf(rv[i].z); p[3] = f2tf(rv[i].w);
        uint32_t* q = &Bs[0][soff[i]];
        q[0] = f2tf(rv[2+i].x); q[1] = f2tf(rv[2+i].y); q[2] = f2tf(rv[2+i].z); q[3] = f2tf(rv[2+i].w);
    }
    __syncthreads();

    const int NKT = HH / 16;
    for (int kt = 0; kt < NKT; kt++) {
        int cb = kt & 1;
        if (kt + 1 < NKT) {
            #pragma unroll
            for (int i = 0; i < 4; i++)
                rv[i] = *(const float4*)(gp[i] + (kt + 1) * 16);
        }
        #pragma unroll
        for (int kk = 0; kk < 2; kk++) {
            uint32_t af[4][4], bf[4][2];
            const int c  = kk * 8 + (lane & 3);
            const int rA = wm + (lane >> 2);
            #pragma unroll
            for (int mt = 0; mt < 4; mt++) {
                int r = rA + mt * 16;
                af[mt][0] = As[cb][r * XST + c];
                af[mt][1] = As[cb][(r + 8) * XST + c];
                af[mt][2] = As[cb][r * XST + c + 4];
                af[mt][3] = As[cb][(r + 8) * XST + c + 4];
            }
            const int rB = wn + (lane >> 2);
            #pragma unroll
            for (int nt = 0; nt < 4; nt++) {
                int r = rB + nt * 8;
                bf[nt][0] = Bs[cb][r * XST + c];
                bf[nt][1] = Bs[cb][r * XST + c + 4];
            }
            #pragma unroll
            for (int mt = 0; mt < 4; mt++)
                #pragma unroll
                for (int nt = 0; nt < 4; nt++)
                    mma_tf32(acc[mt][nt], af[mt], bf[nt]);
        }
        if (kt + 1 < NKT) {
            int nb = cb ^ 1;
            #pragma unroll
            for (int i = 0; i < 2; i++) {
                uint32_t* p = &As[nb][soff[i]];
                p[0] = f2tf(rv[i].x); p[1] = f2tf(rv[i].y); p[2] = f2tf(rv[i].z); p[3] = f2tf(rv[i].w);
                uint32_t* q = &Bs[nb][soff[i]];
                q[0] = f2tf(rv[2+i].x); q[1] = f2tf(rv[2+i].y); q[2] = f2tf(rv[2+i].z); q[3] = f2tf(rv[2+i].w);
            }
            __syncthreads();
        }
    }

    #pragma unroll
    for (int mt = 0; mt < 4; mt++) {
        int r = m0 + wm + mt * 16 + (lane >> 2);
        #pragma unroll
        for (int nt = 0; nt < 4; nt++) {
            int cg = n0 + wn + nt * 8 + (lane & 3) * 2;
            float2 bz = *(const float2*)(bias + cg);
            float2 v0 = make_float2(acc[mt][nt][0] + bz.x, acc[mt][nt][1] + bz.y);
            float2 v1 = make_float2(acc[mt][nt][2] + bz.x, acc[mt][nt][3] + bz.y);
            *(float2*)(xp + (size_t)r * H3 + cg)       = v0;
            *(float2*)(xp + (size_t)(r + 8) * H3 + cg) = v1;
        }
    }
}

// ---------------------------------------------------------------------------
// step v3: 12 warps (m16n16 warp tiles), 8-stage cp.async ring, 2 stages per
// barrier (32 barriers total), prefetch issued right after each barrier.
//   CTA: 32 batches x 96 GEMM cols (3 gates x 32 units), K=1024.
// ---------------------------------------------------------------------------
#define NST   8
#define ROWST 20                   // u32 per smem row (16 + 4 pad)
#define STGU  (128 * ROWST)        // u32 per stage
#define STGB  (STGU * 4)           // bytes per stage (10240)

__global__ __launch_bounds__(384) void step3_kernel(
    const float*    __restrict__ hprev,     // fp32 [B,H]
    const uint32_t* __restrict__ hprev_tf,  // tf32 [B,H]
    const uint32_t* __restrict__ Wh_tf,     // tf32 [3,H,H]
    const float*    __restrict__ bhv,       // [3,H]
    const float*    __restrict__ xp_t,      // [B,3H]
    float* __restrict__ hnext, uint32_t* __restrict__ hnext_tf,
    float* __restrict__ y, int t)
{
    extern __shared__ uint32_t sm[];        // NST * STGU (80 KB)

    const int tid  = threadIdx.x;
    const int lane = tid & 31;
    const int wid  = tid >> 5;              // 0..11
    const int o0   = blockIdx.x * 32;
    const int b0   = blockIdx.y * 32;
    const int wm   = (wid / 6) * 16;        // 0 or 16
    const int wn   = (wid % 6) * 16;        // 0..80

    uint32_t smbase;
    asm("{.reg .u64 tt; cvta.to.shared.u64 tt, %1; cvt.u32.u64 %0, tt;}"
        : "=r"(smbase) : "l"(&sm[0]));

    // cp.async chunk mapping: 512 x 16B chunks per stage.
    // thread tid -> chunk tid; threads 0..127 also chunk 384+tid.
    const uint32_t* gs0; uint32_t sd0;
    const uint32_t* gs1 = nullptr; uint32_t sd1 = 0;
    {
        int c = tid;
        if (c < 128) {
            int row = c >> 2, kv = c & 3;
            gs0 = hprev_tf + (size_t)(b0 + row) * HH + kv * 4;
            sd0 = (uint32_t)(row * ROWST + kv * 4) * 4;
        } else {
            int j = c - 128;
            int row = j >> 2, kv = j & 3;   // row 0..95 = gate*32 + o_local
            gs0 = Wh_tf + ((size_t)(row >> 5) * HH + o0 + (row & 31)) * HH + kv * 4;
            sd0 = (uint32_t)((32 + row) * ROWST + kv * 4) * 4;
        }
        if (tid < 128) {
            int j = tid + 384 - 128;
            int row = j >> 2, kv = j & 3;
            gs1 = Wh_tf + ((size_t)(row >> 5) * HH + o0 + (row & 31)) * HH + kv * 4;
            sd1 = (uint32_t)((32 + row) * ROWST + kv * 4) * 4;
        }
    }

    // Prologue: fill pairs 0,1,2 (stages 0..5), one commit group per pair.
    #pragma unroll
    for (int p = 0; p < 3; p++) {
        #pragma unroll
        for (int ss = 0; ss < 2; ss++) {
            int s = 2 * p + ss;
            uint32_t sb = smbase + (uint32_t)(s & (NST - 1)) * STGB;
            asm volatile("cp.async.cg.shared.global [%0], [%1], 16;"
                         :: "r"(sb + sd0), "l"(gs0 + s * 16));
            if (tid < 128)
                asm volatile("cp.async.cg.shared.global [%0], [%1], 16;"
                             :: "r"(sb + sd1), "l"(gs1 + s * 16));
        }
        asm volatile("cp.async.commit_group;");
    }

    float acc[2][4];
    #pragma unroll
    for (int nt = 0; nt < 2; nt++)
        #pragma unroll
        for (int c = 0; c < 4; c++) acc[nt][c] = 0.f;

    // Invariant ldmatrix address components.
    const int g  = lane >> 3;
    const int r8 = lane & 7;
    const uint32_t aoff = (uint32_t)((wm + (g & 1) * 8 + r8) * ROWST + (g >> 1) * 4) * 4;
    const uint32_t boff = (uint32_t)((32 + wn + (g >> 1) * 8 + r8) * ROWST + (g & 1) * 4) * 4;

    const int NPAIR = HH / 32;  // 32 pairs of K16 stages
    for (int p = 0; p < NPAIR; p++) {
        asm volatile("cp.async.wait_group 2;");
        __syncthreads();

        // Prefetch pair p+3 immediately (overwrites pair p-1's slots).
        if (p < NPAIR - 3) {
            #pragma unroll
            for (int ss = 0; ss < 2; ss++) {
                int s = 2 * (p + 3) + ss;
                uint32_t sb = smbase + (uint32_t)(s & (NST - 1)) * STGB;
                asm volatile("cp.async.cg.shared.global [%0], [%1], 16;"
                             :: "r"(sb + sd0), "l"(gs0 + s * 16));
                if (tid < 128)
                    asm volatile("cp.async.cg.shared.global [%0], [%1], 16;"
                                 :: "r"(sb + sd1), "l"(gs1 + s * 16));
            }
        }
        asm volatile("cp.async.commit_group;");

        // Consume stages 2p and 2p+1.
        #pragma unroll
        for (int ss = 0; ss < 2; ss++) {
            uint32_t sb = smbase + (uint32_t)((2 * p + ss) & (NST - 1)) * STGB;
            #pragma unroll
            for (int kk = 0; kk < 2; kk++) {
                uint32_t kb = (uint32_t)kk * 32;
                uint32_t af[4], bf[4];
                ldsm4(af[0], af[1], af[2], af[3], sb + aoff + kb);
                ldsm4(bf[0], bf[1], bf[2], bf[3], sb + boff + kb);
                mma_tf32(acc[0], af, &bf[0]);
                mma_tf32(acc[1], af, &bf[2]);
            }
        }
    }
    __syncthreads();  // all fragment reads done -> safe to alias smem slot 0

    // Scatter accumulators: Cs[32][100] fp32 (12.8 KB, slots 0-1 region).
    float* Cs = (float*)sm;
    #pragma unroll
    for (int nt = 0; nt < 2; nt++) {
        int r = wm + (lane >> 2);
        int c = wn + nt * 8 + (lane & 3) * 2;
        Cs[r * 100 + c]           = acc[nt][0];
        Cs[r * 100 + c + 1]       = acc[nt][1];
        Cs[(r + 8) * 100 + c]     = acc[nt][2];
        Cs[(r + 8) * 100 + c + 1] = acc[nt][3];
    }
    __syncthreads();

    // Gate fusion: threads 0..255, each -> (batch b, 4 consecutive units).
    if (tid < 256) {
        const int b  = tid >> 3;
        const int oq = (tid & 7) * 4;
        const int bg = b0 + b;
        const int og = o0 + oq;
        const float* xpr = xp_t + (size_t)bg * H3;

        float4 xr4 = *(const float4*)(xpr + og);
        float4 xz4 = *(const float4*)(xpr + HH + og);
        float4 xn4 = *(const float4*)(xpr + 2 * HH + og);
        float4 br4 = *(const float4*)(bhv + og);
        float4 bz4 = *(const float4*)(bhv + HH + og);
        float4 bn4 = *(const float4*)(bhv + 2 * HH + og);
        float4 hp4 = *(const float4*)(hprev + (size_t)bg * HH + og);

        float hv[4];
        #pragma unroll
        for (int j = 0; j < 4; j++) {
            int o = oq + j;
            float hr = Cs[b * 100 + o]      + ((const float*)&br4)[j];
            float hz = Cs[b * 100 + 32 + o] + ((const float*)&bz4)[j];
            float hn = Cs[b * 100 + 64 + o] + ((const float*)&bn4)[j];
            float r  = 1.f / (1.f + __expf(-(((const float*)&xr4)[j] + hr)));
            float z  = 1.f / (1.f + __expf(-(((const float*)&xz4)[j] + hz)));
            float n  = tanhf(((const float*)&xn4)[j] + r * hn);
            hv[j] = (1.f - z) * n + z * ((const float*)&hp4)[j];
        }
        *(float4*)(hnext + (size_t)bg * HH + og) = make_float4(hv[0], hv[1], hv[2], hv[3]);
        *(float4*)(y + ((size_t)bg * TT + t) * HH + og) = make_float4(hv[0], hv[1], hv[2], hv[3]);
        uint4 tf;
        tf.x = f2tf(hv[0]); tf.y = f2tf(hv[1]); tf.z = f2tf(hv[2]); tf.w = f2tf(hv[3]);
        *(uint4*)(hnext_tf + (size_t)bg * HH + og) = tf;
    }
}

// ---------------------------------------------------------------------------
extern "C" void kernel_launch(void* const* d_in, const int* in_sizes, int n_in,
                              void* d_out, int out_size)
{
    (void)in_sizes; (void)n_in; (void)out_size;
    const float* x   = (const float*)d_in[0];  // [B,T,H]
    const float* h0  = (const float*)d_in[1];  // [L,B,H]
    const float* Wx  = (const float*)d_in[2];  // [L,3,H,H]
    const float* Wh  = (const float*)d_in[3];  // [L,3,H,H]
    const float* bx  = (const float*)d_in[4];  // [L,3,H]
    const float* bh  = (const float*)d_in[5];  // [L,3,H]
    float* out   = (float*)d_out;              // [B,T,H] then [L,B,H]
    float* hlast = out + (size_t)BB * TT * HH;

    float*    xp   = nullptr;
    float*    hbuf = nullptr;
    uint32_t* whtf = nullptr;
    uint32_t* htf  = nullptr;
    cudaGetSymbolAddress((void**)&xp,   g_xp);
    cudaGetSymbolAddress((void**)&hbuf, g_hbuf);
    cudaGetSymbolAddress((void**)&whtf, g_whtf);
    cudaGetSymbolAddress((void**)&htf,  g_htf);
    float*    hA  = hbuf;
    float*    hB  = hbuf + BB * HH;
    uint32_t* hAt = htf;
    uint32_t* hBt = htf + BB * HH;

    static bool attr_done = false;
    if (!attr_done) {
        cudaFuncSetAttribute(step3_kernel,
                             cudaFuncAttributeMaxDynamicSharedMemorySize,
                             NST * STGB);
        attr_done = true;
    }

    // Pre-convert Wh (both layers) to tf32.
    {
        int n4 = 2 * 3 * HH * HH / 4;
        cvt_tf32_kernel<<<n4 / 256, 256>>>(Wh, whtf, n4);
    }

    dim3 xgrid(H3 / 128, (BB * TT) / 128);  // (24, 128)
    dim3 sgrid(HH / 32, BB / 32);           // (32, 4)

    for (int l = 0; l < 2; l++) {
        const float* cur = (l == 0) ? x : out;  // layer-1 input = layer-0 output
        xproj_kernel<<<xgrid, 256>>>(cur, Wx + (size_t)l * 3 * HH * HH,
                                     bx + (size_t)l * 3 * HH, xp);
        cudaMemcpyAsync(hA, h0 + (size_t)l * BB * HH, (size_t)BB * HH * sizeof(float),
                        cudaMemcpyDeviceToDevice);
        {
            int n4 = BB * HH / 4;
            cvt_tf32_kernel<<<n4 / 256, 256>>>(h0 + (size_t)l * BB * HH, hAt, n4);
        }
        for (int t = 0; t < TT; t++) {
            const float*    hp  = (t & 1) ? hB  : hA;
            const uint32_t* hpt = (t & 1) ? hBt : hAt;
            float*          hn  = (t & 1) ? hA  : hB;
            uint32_t*       hnt = (t & 1) ? hAt : hBt;
            step3_kernel<<<sgrid, 384, NST * STGB>>>(
                hp, hpt, whtf + (size_t)l * 3 * HH * HH,
                bh + (size_t)l * 3 * HH,
                xp + (size_t)t * BB * H3, hn, hnt, out, t);
        }
        // T=128 even -> final hidden ends up in hA
        cudaMemcpyAsync(hlast + (size_t)l * BB * HH, hA, (size_t)BB * HH * sizeof(float),
                        cudaMemcpyDeviceToDevice);
    }
}